// round 1
// baseline (speedup 1.0000x reference)
#include <cuda_runtime.h>
#include <cstdint>

// Problem constants (fixed shapes for CRF_84868553769207)
#define KTAG 64
#define BTOT 1024
#define TLEN 512
#define START_TAG 62
#define NEGV -10000.0f

// Scratch (allocation-free rule: __device__ globals)
__device__ float g_forward[BTOT];
__device__ float g_gold[BTOT];

// ---------------------------------------------------------------------------
// Forward (log-partition) kernel.
// CTA = 256 threads = 4 batch rows x 64 tags.
// Thread (bl, i) owns alpha[b][i] and row i of E = exp(transitions), packed
// as 32 x f32x2 registers. Per step:
//   m  = max_i alpha          (shfl + smem across the 2 warps of the b-group)
//   v  = exp(alpha - m) -> smem
//   s  = sum_j E[i][j] * v[j] (32 packed fma.rn.f32x2, v pairs via LDS.64 bcast)
//   alpha = m + log(s) + feat[b, t, i]   (feat prefetched one step ahead)
// ---------------------------------------------------------------------------
__global__ void __launch_bounds__(256)
crf_forward_kernel(const float* __restrict__ feats,
                   const float* __restrict__ trans) {
    const int i    = threadIdx.x & 63;   // tag index
    const int bl   = threadIdx.x >> 6;   // batch row within CTA (0..3)
    const int warp = threadIdx.x >> 5;   // 0..7
    const int lane = threadIdx.x & 31;
    const int b    = blockIdx.x * 4 + bl;

    __shared__ __align__(16) float sv[4][KTAG];
    __shared__ float sred[8];
    __shared__ float ssum[8];

    // E row i, packed as f32x2 pairs: E2[jj] = (exp(tr[i][2jj]), exp(tr[i][2jj+1]))
    unsigned long long E2[32];
#pragma unroll
    for (int jj = 0; jj < 32; jj++) {
        float e0 = __expf(trans[i * KTAG + 2 * jj]);
        float e1 = __expf(trans[i * KTAG + 2 * jj + 1]);
        E2[jj] = (unsigned long long)__float_as_uint(e0) |
                 ((unsigned long long)__float_as_uint(e1) << 32);
    }

    float alpha = (i == START_TAG) ? 0.0f : NEGV;

    const float* fb = feats + (size_t)b * TLEN * KTAG + i;
    float fcur = fb[(size_t)1 * KTAG];  // feat for t = 1

    for (int t = 1; t < TLEN; t++) {
        // prefetch next step's emission
        float fnext = (t + 1 < TLEN) ? fb[(size_t)(t + 1) * KTAG] : 0.0f;

        // --- max over the 64 tags of this batch row (2 warps) ---
        float m = alpha;
#pragma unroll
        for (int o = 16; o > 0; o >>= 1)
            m = fmaxf(m, __shfl_xor_sync(0xffffffffu, m, o));
        if (lane == 0) sred[warp] = m;
        __syncthreads();
        m = fmaxf(sred[2 * bl], sred[2 * bl + 1]);

        // --- v = exp(alpha - m) -> shared ---
        sv[bl][i] = __expf(alpha - m);
        __syncthreads();

        // --- s_i = sum_j E[i][j] * v[j], packed f32x2 ---
        unsigned long long acc = 0ull;  // (0.0f, 0.0f)
        const unsigned long long* svp =
            reinterpret_cast<const unsigned long long*>(sv[bl]);
#pragma unroll
        for (int jj = 0; jj < 32; jj++) {
            unsigned long long vv = svp[jj];  // LDS.64 broadcast
            asm("fma.rn.f32x2 %0, %1, %2, %0;"
                : "+l"(acc) : "l"(E2[jj]), "l"(vv));
        }
        float slo = __uint_as_float((unsigned)(acc & 0xffffffffull));
        float shi = __uint_as_float((unsigned)(acc >> 32));
        float s = slo + shi;

        alpha = m + __logf(s) + fcur;
        fcur = fnext;
    }

    // forward_score[b] = logsumexp_i(alpha)
    float m = alpha;
#pragma unroll
    for (int o = 16; o > 0; o >>= 1)
        m = fmaxf(m, __shfl_xor_sync(0xffffffffu, m, o));
    if (lane == 0) sred[warp] = m;
    __syncthreads();
    m = fmaxf(sred[2 * bl], sred[2 * bl + 1]);

    float e = __expf(alpha - m);
#pragma unroll
    for (int o = 16; o > 0; o >>= 1)
        e += __shfl_xor_sync(0xffffffffu, e, o);
    if (lane == 0) ssum[warp] = e;
    __syncthreads();
    if (i == 0)
        g_forward[b] = m + __logf(ssum[2 * bl] + ssum[2 * bl + 1]);
}

// ---------------------------------------------------------------------------
// Gold-path score: one warp per batch row, lanes stride over t.
// gold[b] = sum_{t=1..T-1} trans[tag_t, tag_{t-1}] + feats[b, t, tag_t]
// ---------------------------------------------------------------------------
__global__ void __launch_bounds__(256)
crf_gold_kernel(const float* __restrict__ feats,
                const int* __restrict__ tags,
                const float* __restrict__ trans) {
    int gwarp = (blockIdx.x * blockDim.x + threadIdx.x) >> 5;
    int lane  = threadIdx.x & 31;
    if (gwarp >= BTOT) return;
    const int b = gwarp;

    const int*   tg = tags + (size_t)b * TLEN;
    const float* fb = feats + (size_t)b * TLEN * KTAG;

    float s = 0.0f;
    for (int t = 1 + lane; t < TLEN; t += 32) {
        int ct = tg[t];
        int pt = tg[t - 1];
        s += trans[ct * KTAG + pt] + fb[(size_t)t * KTAG + ct];
    }
#pragma unroll
    for (int o = 16; o > 0; o >>= 1)
        s += __shfl_xor_sync(0xffffffffu, s, o);
    if (lane == 0) g_gold[b] = s;
}

// ---------------------------------------------------------------------------
// Final deterministic reduction: mean(forward - gold) over B.
// ---------------------------------------------------------------------------
__global__ void __launch_bounds__(256)
crf_reduce_kernel(float* __restrict__ out) {
    __shared__ float sh[8];
    int tid  = threadIdx.x;
    int warp = tid >> 5;
    int lane = tid & 31;

    float s = 0.0f;
    for (int x = tid; x < BTOT; x += 256)
        s += g_forward[x] - g_gold[x];
#pragma unroll
    for (int o = 16; o > 0; o >>= 1)
        s += __shfl_xor_sync(0xffffffffu, s, o);
    if (lane == 0) sh[warp] = s;
    __syncthreads();
    if (tid == 0) {
        float tot = 0.0f;
#pragma unroll
        for (int w = 0; w < 8; w++) tot += sh[w];
        out[0] = tot / (float)BTOT;
    }
}

extern "C" void kernel_launch(void* const* d_in, const int* in_sizes, int n_in,
                              void* d_out, int out_size) {
    const float* feats = (const float*)d_in[0];
    const int*   tags  = (const int*)d_in[1];
    const float* trans = (const float*)d_in[2];
    float* out = (float*)d_out;

    // independent gold-score gather (overlaps forward's stream of feats)
    crf_gold_kernel<<<BTOT / 8, 256>>>(feats, tags, trans);
    // forward recurrence: 4 batch rows per 256-thread CTA
    crf_forward_kernel<<<BTOT / 4, 256>>>(feats, trans);
    // scalar mean
    crf_reduce_kernel<<<1, 256>>>(out);
}

// round 2
// speedup vs baseline: 1.1088x; 1.1088x over previous
#include <cuda_runtime.h>
#include <cstdint>

#define KTAG 64
#define BTOT 1024
#define TLEN 512
#define START_TAG 62
#define NEGV -10000.0f

// Scratch (allocation-free rule: __device__ globals)
__device__ float g_forward[BTOT];
__device__ float g_goldp[BTOT * 2];

typedef unsigned long long ull;

__device__ __forceinline__ ull pk2(float x, float y) {
    return (ull)__float_as_uint(x) | ((ull)__float_as_uint(y) << 32);
}
__device__ __forceinline__ float lo2(ull v) { return __uint_as_float((unsigned)v); }
__device__ __forceinline__ float hi2(ull v) { return __uint_as_float((unsigned)(v >> 32)); }

#define FMA2(acc, a, b) asm("fma.rn.f32x2 %0, %1, %2, %0;" : "+l"(acc) : "l"(a), "l"(b))
#define ADD2(d, a, b)   asm("add.rn.f32x2 %0, %1, %2;" : "=l"(d) : "l"(a), "l"(b))

// ---------------------------------------------------------------------------
// Forward (log-partition) kernel.
// One warp per batch row. Lane l owns tags i0=2l, i1=2l+1 and their E-rows
// (E = exp(transitions)) packed as f32x2 in 128 registers.
// Per step (no CTA barriers, single __syncwarp):
//   r  = shfl(alpha[tag0], 0)                   (shift; exact max not needed)
//   v  = exp(alpha - r)  -> smem (double-buffered), STS.64
//   s_i = sum_j E[i][j]*v[j]   (2 rows x 16 LDS.128 + 32 f32x2 FMA)
//   alpha_i = r + log(s_i) + feat[b,t,i]        (feat prefetched, LDG.64)
// t = 1 is computed exactly: alpha1[i] = trans[i,START] + feat1[i].
// ---------------------------------------------------------------------------
__global__ void __launch_bounds__(128, 2)
crf_forward_kernel(const float* __restrict__ feats,
                   const float* __restrict__ trans) {
    const int lane = threadIdx.x & 31;
    const int w    = threadIdx.x >> 5;          // batch row within CTA (0..3)
    const int b    = blockIdx.x * 4 + w;
    const int i0   = 2 * lane;
    const int i1   = 2 * lane + 1;

    __shared__ __align__(16) float sv[4][2][KTAG];

    // E rows for tags i0, i1, packed as f32x2 pairs over j
    ull E0[32], E1[32];
#pragma unroll
    for (int jj = 0; jj < 32; jj++) {
        float a0 = __expf(trans[i0 * KTAG + 2 * jj]);
        float a1 = __expf(trans[i0 * KTAG + 2 * jj + 1]);
        E0[jj] = pk2(a0, a1);
        float b0 = __expf(trans[i1 * KTAG + 2 * jj]);
        float b1 = __expf(trans[i1 * KTAG + 2 * jj + 1]);
        E1[jj] = pk2(b0, b1);
    }

    const float* fb = feats + (size_t)b * TLEN * KTAG;

    // t = 1 exact (only START has finite alpha0)
    float2 f1 = *(const float2*)(fb + 1 * KTAG + i0);
    float a0 = trans[i0 * KTAG + START_TAG] + f1.x;
    float a1 = trans[i1 * KTAG + START_TAG] + f1.y;

    float2 fnext = *(const float2*)(fb + 2 * KTAG + i0);

    for (int t = 2; t < TLEN; t++) {
        float2 fcur = fnext;
        int tn = (t + 1 < TLEN) ? (t + 1) : (TLEN - 1);
        fnext = *(const float2*)(fb + (size_t)tn * KTAG + i0);

        // shift reference: alpha of tag 0 (always finite after t=1)
        float r = __shfl_sync(0xffffffffu, a0, 0);

        int buf = t & 1;
        float v0 = __expf(a0 - r);
        float v1 = __expf(a1 - r);
        *(float2*)&sv[w][buf][i0] = make_float2(v0, v1);
        __syncwarp();

        const ulonglong2* vp = (const ulonglong2*)sv[w][buf];
        ull c0 = 0, c1 = 0, c2 = 0, c3 = 0;   // row i0 accumulators
        ull d0 = 0, d1 = 0, d2 = 0, d3 = 0;   // row i1 accumulators
#pragma unroll
        for (int q = 0; q < 16; q++) {
            ulonglong2 vv = vp[q];            // LDS.128 broadcast: v pairs 2q, 2q+1
            switch (q & 3) {
                case 0: FMA2(c0, E0[2*q], vv.x); FMA2(c1, E0[2*q+1], vv.y);
                        FMA2(d0, E1[2*q], vv.x); FMA2(d1, E1[2*q+1], vv.y); break;
                case 1: FMA2(c2, E0[2*q], vv.x); FMA2(c3, E0[2*q+1], vv.y);
                        FMA2(d2, E1[2*q], vv.x); FMA2(d3, E1[2*q+1], vv.y); break;
                case 2: FMA2(c0, E0[2*q], vv.x); FMA2(c1, E0[2*q+1], vv.y);
                        FMA2(d0, E1[2*q], vv.x); FMA2(d1, E1[2*q+1], vv.y); break;
                default:FMA2(c2, E0[2*q], vv.x); FMA2(c3, E0[2*q+1], vv.y);
                        FMA2(d2, E1[2*q], vv.x); FMA2(d3, E1[2*q+1], vv.y); break;
            }
        }
        ull sA, sB, sC;
        ADD2(sA, c0, c1); ADD2(sB, c2, c3); ADD2(sC, sA, sB);
        float s0 = lo2(sC) + hi2(sC);
        ADD2(sA, d0, d1); ADD2(sB, d2, d3); ADD2(sC, sA, sB);
        float s1 = lo2(sC) + hi2(sC);

        a0 = r + __logf(s0) + fcur.x;
        a1 = r + __logf(s1) + fcur.y;
    }

    // forward_score[b] = logsumexp over the 64 tags (exact max, once)
    float m = fmaxf(a0, a1);
#pragma unroll
    for (int o = 16; o > 0; o >>= 1)
        m = fmaxf(m, __shfl_xor_sync(0xffffffffu, m, o));
    float e = __expf(a0 - m) + __expf(a1 - m);
#pragma unroll
    for (int o = 16; o > 0; o >>= 1)
        e += __shfl_xor_sync(0xffffffffu, e, o);
    if (lane == 0) g_forward[b] = m + __logf(e);
}

// ---------------------------------------------------------------------------
// Gold-path score: one warp per (batch row, T-half), deterministic partials.
// ---------------------------------------------------------------------------
__global__ void __launch_bounds__(256)
crf_gold_kernel(const float* __restrict__ feats,
                const int* __restrict__ tags,
                const float* __restrict__ trans) {
    int gw   = (blockIdx.x * blockDim.x + threadIdx.x) >> 5;
    int lane = threadIdx.x & 31;
    int b    = gw >> 1;
    int half = gw & 1;

    const int*   tg  = tags  + (size_t)b * TLEN;
    const float* fbp = feats + (size_t)b * TLEN * KTAG;

    int t0 = half ? (TLEN / 2) : 1;
    int t1 = half ? TLEN : (TLEN / 2);

    float s = 0.0f;
    for (int t = t0 + lane; t < t1; t += 32) {
        int ct = tg[t];
        int pt = tg[t - 1];
        s += trans[ct * KTAG + pt] + fbp[(size_t)t * KTAG + ct];
    }
#pragma unroll
    for (int o = 16; o > 0; o >>= 1)
        s += __shfl_xor_sync(0xffffffffu, s, o);
    if (lane == 0) g_goldp[gw] = s;
}

// ---------------------------------------------------------------------------
// Final deterministic reduction: mean(forward - gold) over B.
// ---------------------------------------------------------------------------
__global__ void __launch_bounds__(256)
crf_reduce_kernel(float* __restrict__ out) {
    __shared__ float sh[8];
    int tid  = threadIdx.x;
    int warp = tid >> 5;
    int lane = tid & 31;

    float s = 0.0f;
    for (int x = tid; x < BTOT; x += 256)
        s += g_forward[x] - (g_goldp[2 * x] + g_goldp[2 * x + 1]);
#pragma unroll
    for (int o = 16; o > 0; o >>= 1)
        s += __shfl_xor_sync(0xffffffffu, s, o);
    if (lane == 0) sh[warp] = s;
    __syncthreads();
    if (tid == 0) {
        float tot = 0.0f;
#pragma unroll
        for (int w = 0; w < 8; w++) tot += sh[w];
        out[0] = tot / (float)BTOT;
    }
}

extern "C" void kernel_launch(void* const* d_in, const int* in_sizes, int n_in,
                              void* d_out, int out_size) {
    const float* feats = (const float*)d_in[0];
    const int*   tags  = (const int*)d_in[1];
    const float* trans = (const float*)d_in[2];
    float* out = (float*)d_out;

    crf_gold_kernel<<<(BTOT * 2) / 8, 256>>>(feats, tags, trans);
    crf_forward_kernel<<<BTOT / 4, 128>>>(feats, trans);
    crf_reduce_kernel<<<1, 256>>>(out);
}

// round 3
// speedup vs baseline: 1.1115x; 1.0024x over previous
#include <cuda_runtime.h>
#include <cstdint>

#define KTAG 64
#define BTOT 1024
#define TLEN 512
#define START_TAG 62

// Scratch (allocation-free rule: __device__ globals)
__device__ float g_forward[BTOT];
__device__ float g_goldp[BTOT * 4];

typedef unsigned long long ull;

__device__ __forceinline__ ull pk2(float x, float y) {
    return (ull)__float_as_uint(x) | ((ull)__float_as_uint(y) << 32);
}
__device__ __forceinline__ float lo2(ull v) { return __uint_as_float((unsigned)v); }
__device__ __forceinline__ float hi2(ull v) { return __uint_as_float((unsigned)(v >> 32)); }
__device__ __forceinline__ float rcpf(float x) {
    float r; asm("rcp.approx.f32 %0, %1;" : "=f"(r) : "f"(x)); return r;
}

#define FMA2(acc, a, b) asm("fma.rn.f32x2 %0, %1, %2, %0;" : "+l"(acc) : "l"(a), "l"(b))
#define ADD2(d, a, b)   asm("add.rn.f32x2 %0, %1, %2;" : "=l"(d) : "l"(a), "l"(b))

// ---------------------------------------------------------------------------
// Forward (log-partition) kernel with deferred normalization.
// One warp per batch row; lane l owns tags i0=2l, i1=2l+1 and their E-rows
// (E = exp(transitions), f32x2-packed, 128 regs).
// Invariant entering step t: smem buf holds w_j with alpha_{t-1,j} = L + log w_j.
// Step t:  s_i   = sum_j E[i,j] * w_j          (16 LDS.128 + 64 FMA2)
//          u_hat ~ sum_j w_j  (sampled half)   (16 ADD2, reuses loads)
//          w'_i  = s_i * exp(feat_t_i) * rcp(u_hat)   (exp prefetched off-path)
//          L    += log(u_hat)                         (off critical path)
// No shfl, no max-reduce, no dependent exp/log in the chain.
// Final: forward = L + log(sum_i s_i * exp(feat_T_i)).
// ---------------------------------------------------------------------------
__global__ void __launch_bounds__(128, 2)
crf_forward_kernel(const float* __restrict__ feats,
                   const float* __restrict__ trans) {
    const int lane = threadIdx.x & 31;
    const int w    = threadIdx.x >> 5;          // row within CTA (0..3)
    const int b    = blockIdx.x * 4 + w;
    const int i0   = 2 * lane;
    const int i1   = 2 * lane + 1;

    __shared__ __align__(16) float sw_[4][2][KTAG];

    // E rows for tags i0, i1 (f32x2 packed over j)
    ull E0[32], E1[32];
#pragma unroll
    for (int jj = 0; jj < 32; jj++) {
        E0[jj] = pk2(__expf(trans[i0 * KTAG + 2 * jj]),
                     __expf(trans[i0 * KTAG + 2 * jj + 1]));
        E1[jj] = pk2(__expf(trans[i1 * KTAG + 2 * jj]),
                     __expf(trans[i1 * KTAG + 2 * jj + 1]));
    }

    const float* fb = feats + (size_t)b * TLEN * KTAG;

    // t = 1 exact: alpha1[i] = trans[i, START] + feat1[i]; w1 = exp(alpha1), L = 0
    float2 f1 = *(const float2*)(fb + 1 * KTAG + i0);
    float a0 = trans[i0 * KTAG + START_TAG] + f1.x;
    float a1 = trans[i1 * KTAG + START_TAG] + f1.y;
    *(float2*)&sw_[w][0][i0] = make_float2(__expf(a0), __expf(a1));
    float L = 0.0f;

    // prefetch feat for t=2 and its exp
    float2 fnext = *(const float2*)(fb + 2 * KTAG + i0);
    float ef0 = __expf(fnext.x), ef1 = __expf(fnext.y);
    __syncwarp();

    // main loop: t = 2 .. 510 produce w_t; t = 511 handled after the loop
    for (int t = 2; t <= TLEN - 2; t++) {
        float efc0 = ef0, efc1 = ef1;
        fnext = *(const float2*)(fb + (size_t)(t + 1) * KTAG + i0);
        ef0 = __expf(fnext.x);
        ef1 = __expf(fnext.y);

        const int rbuf = t & 1;
        const ulonglong2* vp = (const ulonglong2*)sw_[w][rbuf];

        ull c0 = 0, c1 = 0, d0 = 0, d1 = 0, u0 = 0, u1 = 0;
#pragma unroll
        for (int q = 0; q < 16; q++) {
            ulonglong2 vv = vp[q];                // LDS.128 broadcast
            FMA2(c0, E0[2 * q],     vv.x);
            FMA2(c1, E0[2 * q + 1], vv.y);
            FMA2(d0, E1[2 * q],     vv.x);
            FMA2(d1, E1[2 * q + 1], vv.y);
            if (q & 1) { ADD2(u1, u1, vv.y); }    // sampled normalizer (half)
            else       { ADD2(u0, u0, vv.x); }
        }
        ull cs, ds, us;
        ADD2(cs, c0, c1);
        ADD2(ds, d0, d1);
        ADD2(us, u0, u1);
        float s0 = lo2(cs) + hi2(cs);
        float s1 = lo2(ds) + hi2(ds);
        float uu = lo2(us) + hi2(us);

        float r = rcpf(uu);
        L += __logf(uu);                           // off critical path
        *(float2*)&sw_[w][rbuf ^ 1][i0] =
            make_float2(s0 * efc0 * r, s1 * efc1 * r);
        __syncwarp();
    }

    // final step t = 511: forward = L + log(sum_i s_i * exp(f_i))
    {
        const int rbuf = (TLEN - 1) & 1;
        const ulonglong2* vp = (const ulonglong2*)sw_[w][rbuf];
        ull c0 = 0, c1 = 0, d0 = 0, d1 = 0;
#pragma unroll
        for (int q = 0; q < 16; q++) {
            ulonglong2 vv = vp[q];
            FMA2(c0, E0[2 * q],     vv.x);
            FMA2(c1, E0[2 * q + 1], vv.y);
            FMA2(d0, E1[2 * q],     vv.x);
            FMA2(d1, E1[2 * q + 1], vv.y);
        }
        ull cs, ds;
        ADD2(cs, c0, c1);
        ADD2(ds, d0, d1);
        float s0 = lo2(cs) + hi2(cs);
        float s1 = lo2(ds) + hi2(ds);
        // ef0/ef1 hold exp(feat[511]) from the last prefetch
        float z = s0 * ef0 + s1 * ef1;
#pragma unroll
        for (int o = 16; o > 0; o >>= 1)
            z += __shfl_xor_sync(0xffffffffu, z, o);
        if (lane == 0) g_forward[b] = L + __logf(z);
    }
}

// ---------------------------------------------------------------------------
// Gold-path score: 4 T-segments per batch row, deterministic partials.
// ---------------------------------------------------------------------------
__global__ void __launch_bounds__(256)
crf_gold_kernel(const float* __restrict__ feats,
                const int* __restrict__ tags,
                const float* __restrict__ trans) {
    int gw   = (blockIdx.x * blockDim.x + threadIdx.x) >> 5;
    int lane = threadIdx.x & 31;
    int b    = gw >> 2;
    int seg  = gw & 3;

    const int*   tg  = tags  + (size_t)b * TLEN;
    const float* fbp = feats + (size_t)b * TLEN * KTAG;

    int t0 = seg * (TLEN / 4); if (seg == 0) t0 = 1;
    int t1 = (seg + 1) * (TLEN / 4);

    float s = 0.0f;
    for (int t = t0 + lane; t < t1; t += 32) {
        int ct = tg[t];
        int pt = tg[t - 1];
        s += trans[ct * KTAG + pt] + fbp[(size_t)t * KTAG + ct];
    }
#pragma unroll
    for (int o = 16; o > 0; o >>= 1)
        s += __shfl_xor_sync(0xffffffffu, s, o);
    if (lane == 0) g_goldp[gw] = s;
}

// ---------------------------------------------------------------------------
// Final deterministic reduction: mean(forward - gold) over B.
// ---------------------------------------------------------------------------
__global__ void __launch_bounds__(256)
crf_reduce_kernel(float* __restrict__ out) {
    __shared__ float sh[8];
    int tid  = threadIdx.x;
    int warp = tid >> 5;
    int lane = tid & 31;

    float s = 0.0f;
    for (int x = tid; x < BTOT; x += 256) {
        float g = g_goldp[4 * x] + g_goldp[4 * x + 1] +
                  g_goldp[4 * x + 2] + g_goldp[4 * x + 3];
        s += g_forward[x] - g;
    }
#pragma unroll
    for (int o = 16; o > 0; o >>= 1)
        s += __shfl_xor_sync(0xffffffffu, s, o);
    if (lane == 0) sh[warp] = s;
    __syncthreads();
    if (tid == 0) {
        float tot = 0.0f;
#pragma unroll
        for (int w = 0; w < 8; w++) tot += sh[w];
        out[0] = tot / (float)BTOT;
    }
}

extern "C" void kernel_launch(void* const* d_in, const int* in_sizes, int n_in,
                              void* d_out, int out_size) {
    const float* feats = (const float*)d_in[0];
    const int*   tags  = (const int*)d_in[1];
    const float* trans = (const float*)d_in[2];
    float* out = (float*)d_out;

    // forward first: ncu (-s 5 -c 1) lands on this kernel
    crf_forward_kernel<<<BTOT / 4, 128>>>(feats, trans);
    crf_gold_kernel<<<(BTOT * 4) / 8, 256>>>(feats, tags, trans);
    crf_reduce_kernel<<<1, 256>>>(out);
}